// round 14
// baseline (speedup 1.0000x reference)
#include <cuda_runtime.h>
#include <cstdint>

#define BATCH 4
#define SEQ   4096
#define DIM   128
#define BMQ   64           // q rows per CTA
#define BNK   64           // keys per iteration
#define KBYTES (BNK * DIM * 4)          // 32768 (pair-packed, contiguous)
#define VBYTES (BNK * DIM * 4)          // 32768 (pair-packed, contiguous)
#define BUFB   (KBYTES + VBYTES)        // 65536 per stage
#define NSTAGE 3
#define ATTN_SMEM (NSTAGE * BUFB)       // 196608
#define OSTR  136                       // epilogue reduction stride

// qkv smem: X fp32 [64][136] (reused as epilogue staging), W permuted [128][136]
#define XSTR  136
#define QKV_X 0
#define QKV_W (64 * XSTR)
#define QKV_SMEM ((64 * XSTR + 128 * XSTR) * 4)   // 104448 B -> 2 CTAs/SM

// Scratch (allocation-free rule: __device__ globals).
// g_Q rows permuted within-row: d=8k+c+4h stored at p=8k+2c+h.
// g_K pair-packed per 16-key block (kpos). g_V pair-packed per 8-key block (vpos).
__device__ __align__(16) float g_Q[BATCH * SEQ * DIM];
__device__ __align__(16) float g_K[BATCH * SEQ * DIM];
__device__ __align__(16) float g_V[BATCH * SEQ * DIM];

// ───────────────────────── helpers ─────────────────────────
__device__ __forceinline__ uint32_t smem_u32(const void* p) {
    uint32_t a;
    asm("{ .reg .u64 t; cvta.to.shared.u64 t, %1; cvt.u32.u64 %0, t; }" : "=r"(a) : "l"(p));
    return a;
}
__device__ __forceinline__ float to_tf32(float v) {
    uint32_t r;
    asm("cvt.rna.tf32.f32 %0, %1;" : "=r"(r) : "f"(v));
    return __uint_as_float(r);
}
__device__ __forceinline__ void mma8(float* d, const uint32_t* a, float b0, float b1) {
    asm volatile("mma.sync.aligned.m16n8k8.row.col.f32.tf32.tf32.f32 "
                 "{%0,%1,%2,%3}, {%4,%5,%6,%7}, {%8,%9}, {%0,%1,%2,%3};"
                 : "+f"(d[0]), "+f"(d[1]), "+f"(d[2]), "+f"(d[3])
                 : "r"(a[0]), "r"(a[1]), "r"(a[2]), "r"(a[3]),
                   "r"(__float_as_uint(b0)), "r"(__float_as_uint(b1)));
}
#define CP16(dst, src)  asm volatile("cp.async.cg.shared.global [%0], [%1], 16;" :: "r"(dst), "l"(src))
#define CPCOMMIT()      asm volatile("cp.async.commit_group;")
#define CPWAIT1()       asm volatile("cp.async.wait_group 1;" ::: "memory")

// row permutation (Q): d -> 8*(d>>3) + 2*(d&3) + ((d>>2)&1)
__device__ __forceinline__ int permd(int d) {
    return (d & ~7) + 2 * (d & 3) + ((d >> 2) & 1);
}
// K pair-pack: 16-key blocks of 2048 floats; one float4 = 2 B-frags (key, key+8)
__device__ __forceinline__ int kpos(int key, int d) {
    return ((key >> 4) << 11) + ((d >> 3) << 7) + ((key & 7) << 4)
         + ((d & 3) << 2) + (((key >> 3) & 1) << 1) + ((d >> 2) & 1);
}
// V pair-pack: 8-key blocks of 1024 floats; one float4 = 2 B-frags (e-block pair)
__device__ __forceinline__ int vpos(int key, int e) {
    return ((key >> 3) << 10) + ((e >> 4) << 7) + ((e & 7) << 4)
         + ((key & 3) << 2) + (((e >> 3) & 1) << 1) + ((key >> 2) & 1);
}

// ───────────────────────── Kernel 1: QKV via tf32 mma ─────────────────────
// grid (128, 3): blockIdx.y selects W; each CTA does TWO 64-row tiles.
// 2 CTAs/SM (102 KB smem). x hi/lo split computed in registers.
extern "C" __global__ void __launch_bounds__(256, 2)
qkv_kernel(const float* __restrict__ x, const float* __restrict__ Wq,
           const float* __restrict__ Wk, const float* __restrict__ Wv)
{
    extern __shared__ float smf[];
    const int tid  = threadIdx.x;
    const int lane = tid & 31;
    const int wid  = tid >> 5;
    const int g    = lane >> 2;
    const int c    = lane & 3;
    const int wm   = wid >> 1;
    const int wn   = wid & 1;
    const int w    = blockIdx.y;
    const float* W = (w == 0) ? Wq : (w == 1) ? Wk : Wv;

    // stage W (128x128) permuted rows + tf32, once per CTA
#pragma unroll
    for (int it = 0; it < 16; ++it) {
        int e   = it * 256 + tid;
        int row = e >> 5;
        int d0  = (e & 31) * 4;
        float4 v = *(const float4*)(W + (size_t)row * DIM + d0);
        float vv[4] = {v.x, v.y, v.z, v.w};
#pragma unroll
        for (int j = 0; j < 4; ++j)
            smf[QKV_W + row * XSTR + permd(d0 + j)] = to_tf32(vv[j]);
    }

    for (int t = 0; t < 2; ++t) {
        const int r0g = (blockIdx.x * 2 + t) * 64;

        // stage x tile (64x128) raw fp32, coalesced float4 (X region free here)
#pragma unroll
        for (int it = 0; it < 8; ++it) {
            int e   = it * 256 + tid;
            int row = e >> 5;
            int d0  = (e & 31) * 4;
            *(float4*)&smf[QKV_X + row * XSTR + d0] =
                *(const float4*)(x + (size_t)(r0g + row) * DIM + d0);
        }
        __syncthreads();   // x ready (and W ready on t=0)

        // A-fragments: hi/lo computed in registers
        uint32_t qh[16][4], ql[16][4];
        {
            const int r0 = 16 * wm + g, r1 = r0 + 8;
#pragma unroll
            for (int k = 0; k < 16; ++k) {
                float v0 = smf[QKV_X + r0 * XSTR + 8 * k + c];
                float v2 = smf[QKV_X + r0 * XSTR + 8 * k + c + 4];
                float v1 = smf[QKV_X + r1 * XSTR + 8 * k + c];
                float v3 = smf[QKV_X + r1 * XSTR + 8 * k + c + 4];
                float h0 = to_tf32(v0), h1 = to_tf32(v1), h2 = to_tf32(v2), h3 = to_tf32(v3);
                qh[k][0] = __float_as_uint(h0); qh[k][1] = __float_as_uint(h1);
                qh[k][2] = __float_as_uint(h2); qh[k][3] = __float_as_uint(h3);
                ql[k][0] = __float_as_uint(v0 - h0); ql[k][1] = __float_as_uint(v1 - h1);
                ql[k][2] = __float_as_uint(v2 - h2); ql[k][3] = __float_as_uint(v3 - h3);
            }
        }

        float acc[8][4];
#pragma unroll
        for (int nb = 0; nb < 8; ++nb)
#pragma unroll
            for (int e = 0; e < 4; ++e) acc[nb][e] = 0.f;

        const float2* W2 = (const float2*)(smf + QKV_W);
#pragma unroll
        for (int k = 0; k < 16; ++k) {
#pragma unroll
            for (int nb = 0; nb < 8; ++nb) {
                float2 tt = W2[(64 * wn + 8 * nb + g) * (XSTR / 2) + 4 * k + c];
                mma8(acc[nb], qh[k], tt.x, tt.y);
                mma8(acc[nb], ql[k], tt.x, tt.y);
            }
        }
        __syncthreads();   // all frag loads of X done; X region reusable for staging

        // epilogue: stage 64x128 tile into smem in FINAL layout, then coalesced copy
        float* Sg = smf + QKV_X;
        const float scl = (w == 0) ? 0.08838834764831845f : 1.0f;  // 1/sqrt(128) in Q
        const int l0 = 16 * wm + g;
        const int l1 = l0 + 8;
        if (w == 0) {
            const int wlo = 2 * ((2 * c) & 3) + (c >> 1);
#pragma unroll
            for (int nb = 0; nb < 8; ++nb) {
                int pb = 8 * (8 * wn + nb) + wlo;
                Sg[l0 * DIM + pb]     = to_tf32(acc[nb][0] * scl);
                Sg[l0 * DIM + pb + 2] = to_tf32(acc[nb][1] * scl);
                Sg[l1 * DIM + pb]     = to_tf32(acc[nb][2] * scl);
                Sg[l1 * DIM + pb + 2] = to_tf32(acc[nb][3] * scl);
            }
        } else if (w == 1) {
#pragma unroll
            for (int nb = 0; nb < 8; ++nb) {
                int e0 = 64 * wn + 8 * nb + 2 * c;
                Sg[kpos(l0, e0)]     = to_tf32(acc[nb][0]);
                Sg[kpos(l0, e0 + 1)] = to_tf32(acc[nb][1]);
                Sg[kpos(l1, e0)]     = to_tf32(acc[nb][2]);
                Sg[kpos(l1, e0 + 1)] = to_tf32(acc[nb][3]);
            }
        } else {
#pragma unroll
            for (int nb = 0; nb < 8; ++nb) {
                int e0 = 64 * wn + 8 * nb + 2 * c;
                Sg[vpos(l0, e0)]     = to_tf32(acc[nb][0]);
                Sg[vpos(l0, e0 + 1)] = to_tf32(acc[nb][1]);
                Sg[vpos(l1, e0)]     = to_tf32(acc[nb][2]);
                Sg[vpos(l1, e0 + 1)] = to_tf32(acc[nb][3]);
            }
        }
        __syncthreads();

        // all three layouts are contiguous 32 KB at base + r0g*DIM
        float* dstb = ((w == 0) ? g_Q : (w == 1) ? g_K : g_V) + (size_t)r0g * DIM;
        const float4* S4 = (const float4*)Sg;
        float4* D4 = (float4*)dstb;
#pragma unroll
        for (int j = 0; j < 8; ++j)
            D4[j * 256 + tid] = S4[j * 256 + tid];
        __syncthreads();   // copy done before next tile overwrites X region
    }
}

// ───────────────────────── Kernel 2: mma.sync tf32 flash attention ────────
__device__ __forceinline__ void issue_tile(uint32_t sb, int stage, int tid,
                                           const float* Kg, const float* Vg, int k0)
{
    uint32_t kdst = sb + (uint32_t)stage * BUFB + (uint32_t)tid * 16;
    const char* ksrc = (const char*)(Kg + (size_t)k0 * DIM) + (uint32_t)tid * 16;
    uint32_t vdst = kdst + KBYTES;
    const char* vsrc = (const char*)(Vg + (size_t)k0 * DIM) + (uint32_t)tid * 16;
#pragma unroll
    for (int j = 0; j < 8; ++j) {
        CP16(kdst + j * 4096, ksrc + j * 4096);
        CP16(vdst + j * 4096, vsrc + j * 4096);
    }
}

extern "C" __global__ void __launch_bounds__(256, 1)
attn_kernel(float* __restrict__ out)
{
    extern __shared__ float sm[];
    const uint32_t sb = smem_u32(sm);

    const int tid  = threadIdx.x;
    const int lane = tid & 31;
    const int wid  = tid >> 5;
    const int g    = lane >> 2;
    const int c    = lane & 3;
    const int wm   = wid >> 1;
    const int wn   = wid & 1;
    const int b    = blockIdx.x & 3;
    const int qt   = 63 - (blockIdx.x >> 2);   // longest CTAs first
    const int q0   = qt * BMQ;
    const int nkt  = qt + 1;

    const float* Kg = g_K + (size_t)b * SEQ * DIM;
    const float* Vg = g_V + (size_t)b * SEQ * DIM;

    // Q resident as A-fragments (permuted g_Q -> aligned float2 loads)
    uint32_t qa[16][4];
    {
        const float2* Qp = (const float2*)(g_Q + ((size_t)b * SEQ + q0) * DIM);
        const int r0 = 16 * wm + g, r1 = r0 + 8;
#pragma unroll
        for (int k = 0; k < 16; ++k) {
            float2 u0 = Qp[r0 * 64 + 4 * k + c];
            float2 u1 = Qp[r1 * 64 + 4 * k + c];
            qa[k][0] = __float_as_uint(u0.x); qa[k][2] = __float_as_uint(u0.y);
            qa[k][1] = __float_as_uint(u1.x); qa[k][3] = __float_as_uint(u1.y);
        }
    }

    float oacc[16][4];
#pragma unroll
    for (int nd = 0; nd < 16; ++nd)
#pragma unroll
        for (int e = 0; e < 4; ++e) oacc[nd][e] = 0.f;
    float lsA = 0.f, lsB = 0.f;

    // 3-stage prologue: stages 0,1 (one commit group per stage)
    issue_tile(sb, 0, tid, Kg, Vg, 0);
    CPCOMMIT();
    issue_tile(sb, 1, tid, Kg, Vg, (1 < nkt ? 1 : nkt - 1) * BNK);
    CPCOMMIT();

    int stage = 0;
    for (int kt = 0; kt < nkt; ++kt) {
        CPWAIT1();           // stage (kt%3) complete (newest pending allowed)
        __syncthreads();     // data visible to all; all warps done reading stage (kt+2)%3

        // refill stage (kt+2)%3 for tile kt+2 (clamped; redundant loads harmless)
        {
            int s2 = stage + 2; if (s2 >= NSTAGE) s2 -= NSTAGE;
            int kf = kt + 2; if (kf > nkt - 1) kf = nkt - 1;
            issue_tile(sb, s2, tid, Kg, Vg, kf * BNK);
            CPCOMMIT();
        }

        const float4* Kb4 = (const float4*)(sm + stage * (BUFB / 4));
        const float4* Vb4 = Kb4 + (KBYTES / 16);

        // S = Q . K^T  (one LDS.128 -> two B-fragments; depth-2 prefetch)
        float sacc[4][4];
#pragma unroll
        for (int n = 0; n < 4; ++n)
#pragma unroll
            for (int e = 0; e < 4; ++e) sacc[n][e] = 0.f;

        const float4* kq0 = Kb4 + (2 * wn) * 512 + g * 4 + c;
        const float4* kq1 = kq0 + 512;
        float4 f00 = kq0[0],  f01 = kq1[0];
        float4 f10 = kq0[32], f11 = kq1[32];
#pragma unroll
        for (int k = 0; k < 16; ++k) {
            float4 a0, a1;
            if ((k & 1) == 0) { a0 = f00; a1 = f01; } else { a0 = f10; a1 = f11; }
            if (k < 14) {
                if ((k & 1) == 0) { f00 = kq0[(k + 2) * 32]; f01 = kq1[(k + 2) * 32]; }
                else              { f10 = kq0[(k + 2) * 32]; f11 = kq1[(k + 2) * 32]; }
            }
            mma8(sacc[0], qa[k], a0.x, a0.y);
            mma8(sacc[1], qa[k], a0.z, a0.w);
            mma8(sacc[2], qa[k], a1.x, a1.y);
            mma8(sacc[3], qa[k], a1.z, a1.w);
        }

        // softmax weights (no max subtraction; mask only on diagonal tile)
        const bool diag = (kt == qt);
        const int r0l = 16 * wm + g, r1l = r0l + 8;
#pragma unroll
        for (int n = 0; n < 4; ++n) {
            float e0, e1, e2, e3;
            if (!diag) {
                e0 = __expf(sacc[n][0]); e1 = __expf(sacc[n][1]);
                e2 = __expf(sacc[n][2]); e3 = __expf(sacc[n][3]);
            } else {
                int kl = 32 * wn + 8 * n + 2 * c;
                e0 = (kl     <= r0l) ? __expf(sacc[n][0]) : 0.f;
                e1 = (kl + 1 <= r0l) ? __expf(sacc[n][1]) : 0.f;
                e2 = (kl     <= r1l) ? __expf(sacc[n][2]) : 0.f;
                e3 = (kl + 1 <= r1l) ? __expf(sacc[n][3]) : 0.f;
            }
            lsA += e0 + e1;
            lsB += e2 + e3;
            sacc[n][0] = e0; sacc[n][1] = e1; sacc[n][2] = e2; sacc[n][3] = e3;
        }

        // O += P . V  (shuffle C->A frag; depth-2 prefetch on V stream)
#pragma unroll
        for (int j = 0; j < 4; ++j) {
            const int s1 = (lane & 28) | (c >> 1);
            const int s2 = s1 | 2;
            float w00 = __shfl_sync(0xffffffffu, sacc[j][0], s1);
            float w01 = __shfl_sync(0xffffffffu, sacc[j][1], s1);
            float w02 = __shfl_sync(0xffffffffu, sacc[j][0], s2);
            float w03 = __shfl_sync(0xffffffffu, sacc[j][1], s2);
            float w10 = __shfl_sync(0xffffffffu, sacc[j][2], s1);
            float w11 = __shfl_sync(0xffffffffu, sacc[j][3], s1);
            float w12 = __shfl_sync(0xffffffffu, sacc[j][2], s2);
            float w13 = __shfl_sync(0xffffffffu, sacc[j][3], s2);
            const bool odd = (c & 1);
            uint32_t pa[4];
            pa[0] = __float_as_uint(odd ? w01 : w00);
            pa[1] = __float_as_uint(odd ? w11 : w10);
            pa[2] = __float_as_uint(odd ? w03 : w02);
            pa[3] = __float_as_uint(odd ? w13 : w12);

            const float4* vp = Vb4 + (4 * wn + j) * 256 + g * 4 + c;
            float4 v0 = vp[0], v1 = vp[32];
#pragma unroll
            for (int P = 0; P < 8; ++P) {
                float4 t = ((P & 1) == 0) ? v0 : v1;
                if (P < 6) {
                    if ((P & 1) == 0) v0 = vp[(P + 2) * 32];
                    else              v1 = vp[(P + 2) * 32];
                }
                mma8(oacc[2 * P],     pa, t.x, t.y);
                mma8(oacc[2 * P + 1], pa, t.z, t.w);
            }
        }

        ++stage; if (stage >= NSTAGE) stage = 0;
        // (no second barrier: next iteration's top barrier orders buffer reuse)
    }

    // row-sum reduce across the 4 lanes of each row group
    lsA += __shfl_xor_sync(0xffffffffu, lsA, 1);
    lsA += __shfl_xor_sync(0xffffffffu, lsA, 2);
    lsB += __shfl_xor_sync(0xffffffffu, lsB, 1);
    lsB += __shfl_xor_sync(0xffffffffu, lsB, 2);

    __syncthreads();   // all compute done before reusing smem for reduction

    // cross-wn reduction of O and l through smem
    float* Ob = sm;                 // [64][OSTR]
    float* Lb = sm + 64 * OSTR;     // [128]
    const int lr0 = 16 * wm + g, lr1 = lr0 + 8;

    if (wn == 1) {
#pragma unroll
        for (int nd = 0; nd < 16; ++nd) {
            Ob[lr0 * OSTR + 8 * nd + 2 * c]     = oacc[nd][0];
            Ob[lr0 * OSTR + 8 * nd + 2 * c + 1] = oacc[nd][1];
            Ob[lr1 * OSTR + 8 * nd + 2 * c]     = oacc[nd][2];
            Ob[lr1 * OSTR + 8 * nd + 2 * c + 1] = oacc[nd][3];
        }
        if (c == 0) { Lb[lr0] = lsA; Lb[lr1] = lsB; }
    }
    __syncthreads();
    if (wn == 0) {
        const float invA = 1.0f / (lsA + Lb[lr0]);
        const float invB = 1.0f / (lsB + Lb[lr1]);
        float* o0 = out + ((size_t)b * SEQ + q0 + lr0) * DIM;
        float* o1 = out + ((size_t)b * SEQ + q0 + lr1) * DIM;
#pragma unroll
        for (int nd = 0; nd < 16; ++nd) {
            float2 v0, v1;
            v0.x = (oacc[nd][0] + Ob[lr0 * OSTR + 8 * nd + 2 * c])     * invA;
            v0.y = (oacc[nd][1] + Ob[lr0 * OSTR + 8 * nd + 2 * c + 1]) * invA;
            v1.x = (oacc[nd][2] + Ob[lr1 * OSTR + 8 * nd + 2 * c])     * invB;
            v1.y = (oacc[nd][3] + Ob[lr1 * OSTR + 8 * nd + 2 * c + 1]) * invB;
            *(float2*)(o0 + 8 * nd + 2 * c) = v0;
            *(float2*)(o1 + 8 * nd + 2 * c) = v1;
        }
    }
}

// ───────────────────────── launcher ───────────────────────────────────────
extern "C" void kernel_launch(void* const* d_in, const int* in_sizes, int n_in,
                              void* d_out, int out_size)
{
    const float* x  = (const float*)d_in[0];
    const float* Wq = (const float*)d_in[1];
    const float* Wk = (const float*)d_in[2];
    const float* Wv = (const float*)d_in[3];
    float* out = (float*)d_out;

    cudaFuncSetAttribute(qkv_kernel,  cudaFuncAttributeMaxDynamicSharedMemorySize, QKV_SMEM);
    cudaFuncSetAttribute(attn_kernel, cudaFuncAttributeMaxDynamicSharedMemorySize, ATTN_SMEM);

    qkv_kernel<<<dim3(128, 3), 256, QKV_SMEM>>>(x, Wq, Wk, Wv);
    attn_kernel<<<BATCH * (SEQ / BMQ), 256, ATTN_SMEM>>>(out);
}

// round 15
// speedup vs baseline: 1.5407x; 1.5407x over previous
#include <cuda_runtime.h>
#include <cstdint>

#define BATCH 4
#define SEQ   4096
#define DIM   128
#define BMQ   64           // q rows per CTA
#define BNK   64           // keys per iteration
#define KBYTES (BNK * DIM * 4)          // 32768 (pair-packed, contiguous)
#define VBYTES (BNK * DIM * 4)          // 32768 (pair-packed, contiguous)
#define BUFB   (KBYTES + VBYTES)        // 65536 per stage
#define NSTAGE 3
#define ATTN_SMEM (NSTAGE * BUFB)       // 196608
#define OSTR  136                       // epilogue reduction stride

// qkv smem: X raw fp32 [64][132] (reused as epilogue staging), W permuted [128][136]
#define XSTRX 132
#define WSTR  136
#define QKV_X 0
#define QKV_W (64 * XSTRX)
#define QKV_SMEM ((64 * XSTRX + 128 * WSTR) * 4)   // 103424 B -> 2 CTAs/SM

// Scratch (allocation-free rule: __device__ globals).
// g_Q rows permuted within-row: d=8k+c+4h stored at p=8k+2c+h.
// g_K pair-packed per 16-key block (kpos). g_V pair-packed per 8-key block (vpos).
__device__ __align__(16) float g_Q[BATCH * SEQ * DIM];
__device__ __align__(16) float g_K[BATCH * SEQ * DIM];
__device__ __align__(16) float g_V[BATCH * SEQ * DIM];

// ───────────────────────── helpers ─────────────────────────
__device__ __forceinline__ uint32_t smem_u32(const void* p) {
    uint32_t a;
    asm("{ .reg .u64 t; cvta.to.shared.u64 t, %1; cvt.u32.u64 %0, t; }" : "=r"(a) : "l"(p));
    return a;
}
__device__ __forceinline__ float to_tf32(float v) {
    uint32_t r;
    asm("cvt.rna.tf32.f32 %0, %1;" : "=r"(r) : "f"(v));
    return __uint_as_float(r);
}
__device__ __forceinline__ void mma8(float* d, const uint32_t* a, float b0, float b1) {
    asm volatile("mma.sync.aligned.m16n8k8.row.col.f32.tf32.tf32.f32 "
                 "{%0,%1,%2,%3}, {%4,%5,%6,%7}, {%8,%9}, {%0,%1,%2,%3};"
                 : "+f"(d[0]), "+f"(d[1]), "+f"(d[2]), "+f"(d[3])
                 : "r"(a[0]), "r"(a[1]), "r"(a[2]), "r"(a[3]),
                   "r"(__float_as_uint(b0)), "r"(__float_as_uint(b1)));
}
#define CP16(dst, src)  asm volatile("cp.async.cg.shared.global [%0], [%1], 16;" :: "r"(dst), "l"(src))
#define CPCOMMIT()      asm volatile("cp.async.commit_group;")
#define CPWAIT1()       asm volatile("cp.async.wait_group 1;" ::: "memory")

// row permutation (Q): d -> 8*(d>>3) + 2*(d&3) + ((d>>2)&1)
__device__ __forceinline__ int permd(int d) {
    return (d & ~7) + 2 * (d & 3) + ((d >> 2) & 1);
}
// K pair-pack: 16-key blocks of 2048 floats; one float4 = 2 B-frags (key, key+8)
__device__ __forceinline__ int kpos(int key, int d) {
    return ((key >> 4) << 11) + ((d >> 3) << 7) + ((key & 7) << 4)
         + ((d & 3) << 2) + (((key >> 3) & 1) << 1) + ((d >> 2) & 1);
}
// V pair-pack: 8-key blocks of 1024 floats; one float4 = 2 B-frags (e-block pair)
__device__ __forceinline__ int vpos(int key, int e) {
    return ((key >> 3) << 10) + ((e >> 4) << 7) + ((e & 7) << 4)
         + ((key & 3) << 2) + (((e >> 3) & 1) << 1) + ((key >> 2) & 1);
}

// ───────────────────────── Kernel 1: QKV via tf32 mma ─────────────────────
// grid (128, 3): blockIdx.y selects W; each CTA does TWO 64-row tiles.
// 2 CTAs/SM (101 KB smem). hi/lo split per-k in registers (no spills).
extern "C" __global__ void __launch_bounds__(256, 2)
qkv_kernel(const float* __restrict__ x, const float* __restrict__ Wq,
           const float* __restrict__ Wk, const float* __restrict__ Wv)
{
    extern __shared__ float smf[];
    const int tid  = threadIdx.x;
    const int lane = tid & 31;
    const int wid  = tid >> 5;
    const int g    = lane >> 2;
    const int c    = lane & 3;
    const int wm   = wid >> 1;
    const int wn   = wid & 1;
    const int w    = blockIdx.y;
    const float* W = (w == 0) ? Wq : (w == 1) ? Wk : Wv;

    // stage W (128x128) permuted rows + tf32, once per CTA
#pragma unroll
    for (int it = 0; it < 16; ++it) {
        int e   = it * 256 + tid;
        int row = e >> 5;
        int d0  = (e & 31) * 4;
        float4 v = *(const float4*)(W + (size_t)row * DIM + d0);
        float vv[4] = {v.x, v.y, v.z, v.w};
#pragma unroll
        for (int j = 0; j < 4; ++j)
            smf[QKV_W + row * WSTR + permd(d0 + j)] = to_tf32(vv[j]);
    }

    for (int t = 0; t < 2; ++t) {
        const int r0g = (blockIdx.x * 2 + t) * 64;

        // stage x tile (64x128) raw fp32, coalesced float4
#pragma unroll
        for (int it = 0; it < 8; ++it) {
            int e   = it * 256 + tid;
            int row = e >> 5;
            int d0  = (e & 31) * 4;
            *(float4*)&smf[QKV_X + row * XSTRX + d0] =
                *(const float4*)(x + (size_t)(r0g + row) * DIM + d0);
        }
        __syncthreads();   // x ready (and W ready on t=0)

        float acc[8][4];
#pragma unroll
        for (int nb = 0; nb < 8; ++nb)
#pragma unroll
            for (int e = 0; e < 4; ++e) acc[nb][e] = 0.f;

        const float2* W2 = (const float2*)(smf + QKV_W);
        const int r0 = 16 * wm + g, r1 = r0 + 8;
#pragma unroll
        for (int k = 0; k < 16; ++k) {
            // current-k x fragments only: 4 scalar LDS (conflict-free, 4g+c banks)
            float v0 = smf[QKV_X + r0 * XSTRX + 8 * k + c];
            float v2 = smf[QKV_X + r0 * XSTRX + 8 * k + c + 4];
            float v1 = smf[QKV_X + r1 * XSTRX + 8 * k + c];
            float v3 = smf[QKV_X + r1 * XSTRX + 8 * k + c + 4];
            float h0 = to_tf32(v0), h1 = to_tf32(v1), h2 = to_tf32(v2), h3 = to_tf32(v3);
            uint32_t qhk[4] = {__float_as_uint(h0), __float_as_uint(h1),
                               __float_as_uint(h2), __float_as_uint(h3)};
            uint32_t qlk[4] = {__float_as_uint(v0 - h0), __float_as_uint(v1 - h1),
                               __float_as_uint(v2 - h2), __float_as_uint(v3 - h3)};
#pragma unroll
            for (int nb = 0; nb < 8; ++nb) {
                float2 tt = W2[(64 * wn + 8 * nb + g) * (WSTR / 2) + 4 * k + c];
                mma8(acc[nb], qhk, tt.x, tt.y);
                mma8(acc[nb], qlk, tt.x, tt.y);
            }
        }
        __syncthreads();   // X reads done; X region reusable for staging

        // epilogue: stage 64x128 tile into smem in FINAL layout, then coalesced copy
        float* Sg = smf + QKV_X;
        const float scl = (w == 0) ? 0.08838834764831845f : 1.0f;  // 1/sqrt(128) in Q
        const int l0 = r0;
        const int l1 = r1;
        if (w == 0) {
            const int wlo = 2 * ((2 * c) & 3) + (c >> 1);
#pragma unroll
            for (int nb = 0; nb < 8; ++nb) {
                int pb = 8 * (8 * wn + nb) + wlo;
                Sg[l0 * DIM + pb]     = to_tf32(acc[nb][0] * scl);
                Sg[l0 * DIM + pb + 2] = to_tf32(acc[nb][1] * scl);
                Sg[l1 * DIM + pb]     = to_tf32(acc[nb][2] * scl);
                Sg[l1 * DIM + pb + 2] = to_tf32(acc[nb][3] * scl);
            }
        } else if (w == 1) {
#pragma unroll
            for (int nb = 0; nb < 8; ++nb) {
                int e0 = 64 * wn + 8 * nb + 2 * c;
                Sg[kpos(l0, e0)]     = to_tf32(acc[nb][0]);
                Sg[kpos(l0, e0 + 1)] = to_tf32(acc[nb][1]);
                Sg[kpos(l1, e0)]     = to_tf32(acc[nb][2]);
                Sg[kpos(l1, e0 + 1)] = to_tf32(acc[nb][3]);
            }
        } else {
#pragma unroll
            for (int nb = 0; nb < 8; ++nb) {
                int e0 = 64 * wn + 8 * nb + 2 * c;
                Sg[vpos(l0, e0)]     = to_tf32(acc[nb][0]);
                Sg[vpos(l0, e0 + 1)] = to_tf32(acc[nb][1]);
                Sg[vpos(l1, e0)]     = to_tf32(acc[nb][2]);
                Sg[vpos(l1, e0 + 1)] = to_tf32(acc[nb][3]);
            }
        }
        __syncthreads();

        // all three layouts are contiguous 32 KB at base + r0g*DIM
        float* dstb = ((w == 0) ? g_Q : (w == 1) ? g_K : g_V) + (size_t)r0g * DIM;
        const float4* S4 = (const float4*)Sg;
        float4* D4 = (float4*)dstb;
#pragma unroll
        for (int j = 0; j < 8; ++j)
            D4[j * 256 + tid] = S4[j * 256 + tid];
        __syncthreads();   // copy done before next tile overwrites X region
    }
}

// ───────────────────────── Kernel 2: mma.sync tf32 flash attention ────────
__device__ __forceinline__ void issue_tile(uint32_t sb, int stage, int tid,
                                           const float* Kg, const float* Vg, int k0)
{
    uint32_t kdst = sb + (uint32_t)stage * BUFB + (uint32_t)tid * 16;
    const char* ksrc = (const char*)(Kg + (size_t)k0 * DIM) + (uint32_t)tid * 16;
    uint32_t vdst = kdst + KBYTES;
    const char* vsrc = (const char*)(Vg + (size_t)k0 * DIM) + (uint32_t)tid * 16;
#pragma unroll
    for (int j = 0; j < 8; ++j) {
        CP16(kdst + j * 4096, ksrc + j * 4096);
        CP16(vdst + j * 4096, vsrc + j * 4096);
    }
}

extern "C" __global__ void __launch_bounds__(256, 1)
attn_kernel(float* __restrict__ out)
{
    extern __shared__ float sm[];
    const uint32_t sb = smem_u32(sm);

    const int tid  = threadIdx.x;
    const int lane = tid & 31;
    const int wid  = tid >> 5;
    const int g    = lane >> 2;
    const int c    = lane & 3;
    const int wm   = wid >> 1;
    const int wn   = wid & 1;
    const int b    = blockIdx.x & 3;
    const int qt   = 63 - (blockIdx.x >> 2);   // longest CTAs first
    const int q0   = qt * BMQ;
    const int nkt  = qt + 1;

    const float* Kg = g_K + (size_t)b * SEQ * DIM;
    const float* Vg = g_V + (size_t)b * SEQ * DIM;

    // Q resident as A-fragments (permuted g_Q -> aligned float2 loads)
    uint32_t qa[16][4];
    {
        const float2* Qp = (const float2*)(g_Q + ((size_t)b * SEQ + q0) * DIM);
        const int r0 = 16 * wm + g, r1 = r0 + 8;
#pragma unroll
        for (int k = 0; k < 16; ++k) {
            float2 u0 = Qp[r0 * 64 + 4 * k + c];
            float2 u1 = Qp[r1 * 64 + 4 * k + c];
            qa[k][0] = __float_as_uint(u0.x); qa[k][2] = __float_as_uint(u0.y);
            qa[k][1] = __float_as_uint(u1.x); qa[k][3] = __float_as_uint(u1.y);
        }
    }

    float oacc[16][4];
#pragma unroll
    for (int nd = 0; nd < 16; ++nd)
#pragma unroll
        for (int e = 0; e < 4; ++e) oacc[nd][e] = 0.f;
    float lsA = 0.f, lsB = 0.f;

    // 3-stage prologue: stages 0,1 (one commit group per stage)
    issue_tile(sb, 0, tid, Kg, Vg, 0);
    CPCOMMIT();
    issue_tile(sb, 1, tid, Kg, Vg, (1 < nkt ? 1 : nkt - 1) * BNK);
    CPCOMMIT();

    int stage = 0;
    for (int kt = 0; kt < nkt; ++kt) {
        CPWAIT1();           // stage (kt%3) complete (newest pending allowed)
        __syncthreads();     // data visible to all; all warps done reading stage (kt+2)%3

        // refill stage (kt+2)%3 for tile kt+2 (clamped; redundant loads harmless)
        {
            int s2 = stage + 2; if (s2 >= NSTAGE) s2 -= NSTAGE;
            int kf = kt + 2; if (kf > nkt - 1) kf = nkt - 1;
            issue_tile(sb, s2, tid, Kg, Vg, kf * BNK);
            CPCOMMIT();
        }

        const float4* Kb4 = (const float4*)(sm + stage * (BUFB / 4));
        const float4* Vb4 = Kb4 + (KBYTES / 16);

        // S = Q . K^T  (one LDS.128 -> two B-fragments; depth-2 prefetch)
        float sacc[4][4];
#pragma unroll
        for (int n = 0; n < 4; ++n)
#pragma unroll
            for (int e = 0; e < 4; ++e) sacc[n][e] = 0.f;

        const float4* kq0 = Kb4 + (2 * wn) * 512 + g * 4 + c;
        const float4* kq1 = kq0 + 512;
        float4 f00 = kq0[0],  f01 = kq1[0];
        float4 f10 = kq0[32], f11 = kq1[32];
#pragma unroll
        for (int k = 0; k < 16; ++k) {
            float4 a0, a1;
            if ((k & 1) == 0) { a0 = f00; a1 = f01; } else { a0 = f10; a1 = f11; }
            if (k < 14) {
                if ((k & 1) == 0) { f00 = kq0[(k + 2) * 32]; f01 = kq1[(k + 2) * 32]; }
                else              { f10 = kq0[(k + 2) * 32]; f11 = kq1[(k + 2) * 32]; }
            }
            mma8(sacc[0], qa[k], a0.x, a0.y);
            mma8(sacc[1], qa[k], a0.z, a0.w);
            mma8(sacc[2], qa[k], a1.x, a1.y);
            mma8(sacc[3], qa[k], a1.z, a1.w);
        }

        // softmax weights (no max subtraction; mask only on diagonal tile)
        const bool diag = (kt == qt);
        const int r0l = 16 * wm + g, r1l = r0l + 8;
#pragma unroll
        for (int n = 0; n < 4; ++n) {
            float e0, e1, e2, e3;
            if (!diag) {
                e0 = __expf(sacc[n][0]); e1 = __expf(sacc[n][1]);
                e2 = __expf(sacc[n][2]); e3 = __expf(sacc[n][3]);
            } else {
                int kl = 32 * wn + 8 * n + 2 * c;
                e0 = (kl     <= r0l) ? __expf(sacc[n][0]) : 0.f;
                e1 = (kl + 1 <= r0l) ? __expf(sacc[n][1]) : 0.f;
                e2 = (kl     <= r1l) ? __expf(sacc[n][2]) : 0.f;
                e3 = (kl + 1 <= r1l) ? __expf(sacc[n][3]) : 0.f;
            }
            lsA += e0 + e1;
            lsB += e2 + e3;
            sacc[n][0] = e0; sacc[n][1] = e1; sacc[n][2] = e2; sacc[n][3] = e3;
        }

        // O += P . V  (shuffle C->A frag; depth-2 prefetch on V stream)
#pragma unroll
        for (int j = 0; j < 4; ++j) {
            const int s1 = (lane & 28) | (c >> 1);
            const int s2 = s1 | 2;
            float w00 = __shfl_sync(0xffffffffu, sacc[j][0], s1);
            float w01 = __shfl_sync(0xffffffffu, sacc[j][1], s1);
            float w02 = __shfl_sync(0xffffffffu, sacc[j][0], s2);
            float w03 = __shfl_sync(0xffffffffu, sacc[j][1], s2);
            float w10 = __shfl_sync(0xffffffffu, sacc[j][2], s1);
            float w11 = __shfl_sync(0xffffffffu, sacc[j][3], s1);
            float w12 = __shfl_sync(0xffffffffu, sacc[j][2], s2);
            float w13 = __shfl_sync(0xffffffffu, sacc[j][3], s2);
            const bool odd = (c & 1);
            uint32_t pa[4];
            pa[0] = __float_as_uint(odd ? w01 : w00);
            pa[1] = __float_as_uint(odd ? w11 : w10);
            pa[2] = __float_as_uint(odd ? w03 : w02);
            pa[3] = __float_as_uint(odd ? w13 : w12);

            const float4* vp = Vb4 + (4 * wn + j) * 256 + g * 4 + c;
            float4 v0 = vp[0], v1 = vp[32];
#pragma unroll
            for (int P = 0; P < 8; ++P) {
                float4 t = ((P & 1) == 0) ? v0 : v1;
                if (P < 6) {
                    if ((P & 1) == 0) v0 = vp[(P + 2) * 32];
                    else              v1 = vp[(P + 2) * 32];
                }
                mma8(oacc[2 * P],     pa, t.x, t.y);
                mma8(oacc[2 * P + 1], pa, t.z, t.w);
            }
        }

        ++stage; if (stage >= NSTAGE) stage = 0;
        // (no second barrier: next iteration's top barrier orders buffer reuse)
    }

    // row-sum reduce across the 4 lanes of each row group
    lsA += __shfl_xor_sync(0xffffffffu, lsA, 1);
    lsA += __shfl_xor_sync(0xffffffffu, lsA, 2);
    lsB += __shfl_xor_sync(0xffffffffu, lsB, 1);
    lsB += __shfl_xor_sync(0xffffffffu, lsB, 2);

    __syncthreads();   // all compute done before reusing smem for reduction

    // cross-wn reduction of O and l through smem
    float* Ob = sm;                 // [64][OSTR]
    float* Lb = sm + 64 * OSTR;     // [128]
    const int lr0 = 16 * wm + g, lr1 = lr0 + 8;

    if (wn == 1) {
#pragma unroll
        for (int nd = 0; nd < 16; ++nd) {
            Ob[lr0 * OSTR + 8 * nd + 2 * c]     = oacc[nd][0];
            Ob[lr0 * OSTR + 8 * nd + 2 * c + 1] = oacc[nd][1];
            Ob[lr1 * OSTR + 8 * nd + 2 * c]     = oacc[nd][2];
            Ob[lr1 * OSTR + 8 * nd + 2 * c + 1] = oacc[nd][3];
        }
        if (c == 0) { Lb[lr0] = lsA; Lb[lr1] = lsB; }
    }
    __syncthreads();
    if (wn == 0) {
        const float invA = 1.0f / (lsA + Lb[lr0]);
        const float invB = 1.0f / (lsB + Lb[lr1]);
        float* o0 = out + ((size_t)b * SEQ + q0 + lr0) * DIM;
        float* o1 = out + ((size_t)b * SEQ + q0 + lr1) * DIM;
#pragma unroll
        for (int nd = 0; nd < 16; ++nd) {
            float2 v0, v1;
            v0.x = (oacc[nd][0] + Ob[lr0 * OSTR + 8 * nd + 2 * c])     * invA;
            v0.y = (oacc[nd][1] + Ob[lr0 * OSTR + 8 * nd + 2 * c + 1]) * invA;
            v1.x = (oacc[nd][2] + Ob[lr1 * OSTR + 8 * nd + 2 * c])     * invB;
            v1.y = (oacc[nd][3] + Ob[lr1 * OSTR + 8 * nd + 2 * c + 1]) * invB;
            *(float2*)(o0 + 8 * nd + 2 * c) = v0;
            *(float2*)(o1 + 8 * nd + 2 * c) = v1;
        }
    }
}

// ───────────────────────── launcher ───────────────────────────────────────
extern "C" void kernel_launch(void* const* d_in, const int* in_sizes, int n_in,
                              void* d_out, int out_size)
{
    const float* x  = (const float*)d_in[0];
    const float* Wq = (const float*)d_in[1];
    const float* Wk = (const float*)d_in[2];
    const float* Wv = (const float*)d_in[3];
    float* out = (float*)d_out;

    cudaFuncSetAttribute(qkv_kernel,  cudaFuncAttributeMaxDynamicSharedMemorySize, QKV_SMEM);
    cudaFuncSetAttribute(attn_kernel, cudaFuncAttributeMaxDynamicSharedMemorySize, ATTN_SMEM);

    qkv_kernel<<<dim3(128, 3), 256, QKV_SMEM>>>(x, Wq, Wk, Wv);
    attn_kernel<<<BATCH * (SEQ / BMQ), 256, ATTN_SMEM>>>(out);
}